// round 6
// baseline (speedup 1.0000x reference)
#include <cuda_runtime.h>
#include <cuda_fp16.h>
#include <mma.h>
#include <cstdint>

using namespace nvcuda;

// Problem constants
#define BB 2
#define NN 10000
#define MM 320000
#define DD 256
#define HH 8
#define ROWS (BB * NN)          // 20000 flattened GEMM rows
#define MPAD 20096              // 157 * 128: padded so GEMM needs no guards
#define TOTAL_E (BB * MM)       // 640000 (b, edge) pairs
#define BK 32
#define LDA 40                  // As padded stride (halves): 80B, conflict-free LDSM
#define LDB 136                 // Bs padded stride (halves): 272B, conflict-free LDSM
#define LDS_STAGE 20            // epilogue staging stride (floats)

// ---------------- scratch (device globals; no allocation allowed) ----------
__device__ __half g_xh[2 * (size_t)MPAD * DD];  // fp16 x_q | x_k (padded rows zeroed)
__device__ __half g_wh[2 * DD * DD];            // fp16 w_q | w_k
__device__ __half g_qh[(size_t)MPAD * DD];      // fp16 q
__device__ __half g_kh[(size_t)MPAD * DD];      // fp16 k
__device__ float  g_seg[(size_t)BB * NN * HH];  // 640 KB
__device__ int    g_mask32[2 * MM];             // canonical int32 mask
__device__ int    g_is64;                       // detected mask dtype

// ---------------- K_pre0: detect mask dtype ---------------------------------
// int64 indices in [0,N): every odd 32-bit word is 0. int32: odd words random.
__global__ void detect_mask_kernel(const unsigned* __restrict__ mraw) {
    __shared__ int any_nonzero;
    if (threadIdx.x == 0) any_nonzero = 0;
    __syncthreads();
    unsigned v = mraw[threadIdx.x * 2 + 1];
    if (v != 0u) atomicOr(&any_nonzero, 1);
    __syncthreads();
    if (threadIdx.x == 0) g_is64 = any_nonzero ? 0 : 1;
}

// ---------------- K_pre1: normalize mask to int32 (clamped) + reset seg -----
__global__ void convert_mask_kernel(const void* __restrict__ mraw) {
    int t = blockIdx.x * blockDim.x + threadIdx.x;
    if (t < 2 * MM) {
        long long v;
        if (g_is64) v = ((const long long*)mraw)[t];
        else        v = (long long)((const int*)mraw)[t];
        int vi = (int)v;
        vi = vi < 0 ? 0 : (vi >= NN ? NN - 1 : vi);
        g_mask32[t] = vi;
    }
    if (t < BB * NN * HH) g_seg[t] = 0.0f;
}

// ---------------- K_pre2: fp32 -> fp16 conversion of x and w ----------------
__global__ void convert_inputs_kernel(const float* __restrict__ xq,
                                      const float* __restrict__ xk,
                                      const float* __restrict__ wq,
                                      const float* __restrict__ wk) {
    const int t = blockIdx.x * blockDim.x + threadIdx.x;
    const int XT = 2 * MPAD * (DD / 8);   // threads covering x region
    if (t < XT) {
        const int per_mat = MPAD * (DD / 8);
        const int mat = t / per_mat;
        const int r   = (t % per_mat) / (DD / 8);
        const int c   = (t % (DD / 8)) * 8;
        __half2 h[4];
        if (r < ROWS) {
            const float* src = (mat == 0 ? xq : xk) + (size_t)r * DD + c;
            float4 f0 = *(const float4*)(src);
            float4 f1 = *(const float4*)(src + 4);
            h[0] = __float22half2_rn(make_float2(f0.x, f0.y));
            h[1] = __float22half2_rn(make_float2(f0.z, f0.w));
            h[2] = __float22half2_rn(make_float2(f1.x, f1.y));
            h[3] = __float22half2_rn(make_float2(f1.z, f1.w));
        } else {
            h[0] = h[1] = h[2] = h[3] = __float2half2_rn(0.0f);
        }
        *(uint4*)(g_xh + (size_t)mat * MPAD * DD + (size_t)r * DD + c) = *(uint4*)h;
    } else {
        const int u = t - XT;
        const int WT = 2 * (DD * DD / 8);
        if (u < WT) {
            const int per_mat = DD * DD / 8;
            const int mat = u / per_mat;
            const int e   = (u % per_mat) * 8;
            const float* src = (mat == 0 ? wq : wk) + e;
            float4 f0 = *(const float4*)(src);
            float4 f1 = *(const float4*)(src + 4);
            __half2 h[4];
            h[0] = __float22half2_rn(make_float2(f0.x, f0.y));
            h[1] = __float22half2_rn(make_float2(f0.z, f0.w));
            h[2] = __float22half2_rn(make_float2(f1.x, f1.y));
            h[3] = __float22half2_rn(make_float2(f1.z, f1.w));
            *(uint4*)(g_wh + (size_t)mat * DD * DD + e) = *(uint4*)h;
        }
    }
}

// ---------------- K1: HMMA GEMM  C = A(fp16) * W(fp16), fp32 acc, fp16 out --
// BM=128, BN=128, BK=32. 8 warps in 4x2, each owns 32x64 (2x4 wmma frags).
// Padded smem strides (LDA=40, LDB=136) -> conflict-free LDSM. Register
// prefetch of next k-tile. No bounds checks (M padded to MPAD).
__global__ void __launch_bounds__(256)
gemm_wmma_kernel() {
    const int mat = blockIdx.z;
    const __half* A = g_xh + (size_t)mat * MPAD * DD;
    const __half* B = g_wh + (size_t)mat * DD * DD;
    __half*       C = (mat == 0) ? g_qh : g_kh;

    __shared__ __half As[128 * LDA];            // padded: 10 KB
    __shared__ __half Bs[BK * LDB];             // padded: 8.5 KB
    __shared__ float  stage[8][16 * LDS_STAGE]; // per-warp staging, 10 KB

    const int tid  = threadIdx.x;
    const int warp = tid >> 5;
    const int lane = tid & 31;
    const int wm = warp >> 1;          // 0..3
    const int wn = warp & 1;           // 0..1
    const int block_row = blockIdx.x * 128;
    const int block_col = blockIdx.y * 128;

    const int a_r = tid >> 1;
    const int a_c = (tid & 1) * 16;
    const __half* a_src = A + (size_t)(block_row + a_r) * DD + a_c;
    const int b_r0 = tid >> 4,          b_c0 = (tid & 15) * 8;
    const int b_r1 = (tid + 256) >> 4,  b_c1 = ((tid + 256) & 15) * 8;
    const __half* b_src0 = B + (size_t)b_r0 * DD + block_col + b_c0;
    const __half* b_src1 = B + (size_t)b_r1 * DD + block_col + b_c1;

    wmma::fragment<wmma::accumulator, 16, 16, 16, float> acc[2][4];
    #pragma unroll
    for (int i = 0; i < 2; i++)
        #pragma unroll
        for (int j = 0; j < 4; j++) wmma::fill_fragment(acc[i][j], 0.0f);

    uint4 av0 = *(const uint4*)(a_src);
    uint4 av1 = *(const uint4*)(a_src + 8);
    uint4 bv0 = *(const uint4*)(b_src0);
    uint4 bv1 = *(const uint4*)(b_src1);

    for (int k0 = 0; k0 < DD; k0 += BK) {
        *(uint4*)(As + a_r * LDA + a_c)     = av0;
        *(uint4*)(As + a_r * LDA + a_c + 8) = av1;
        *(uint4*)(Bs + b_r0 * LDB + b_c0)   = bv0;
        *(uint4*)(Bs + b_r1 * LDB + b_c1)   = bv1;
        __syncthreads();

        if (k0 + BK < DD) {            // issue next tile's loads early
            av0 = *(const uint4*)(a_src + k0 + BK);
            av1 = *(const uint4*)(a_src + k0 + BK + 8);
            bv0 = *(const uint4*)(b_src0 + (size_t)(k0 + BK) * DD);
            bv1 = *(const uint4*)(b_src1 + (size_t)(k0 + BK) * DD);
        }

        #pragma unroll
        for (int kk = 0; kk < BK; kk += 16) {
            wmma::fragment<wmma::matrix_a, 16, 16, 16, __half, wmma::row_major> af[2];
            wmma::fragment<wmma::matrix_b, 16, 16, 16, __half, wmma::row_major> bf[4];
            #pragma unroll
            for (int i = 0; i < 2; i++)
                wmma::load_matrix_sync(af[i], As + (wm * 32 + 16 * i) * LDA + kk, LDA);
            #pragma unroll
            for (int j = 0; j < 4; j++)
                wmma::load_matrix_sync(bf[j], Bs + kk * LDB + wn * 64 + 16 * j, LDB);
            #pragma unroll
            for (int i = 0; i < 2; i++)
                #pragma unroll
                for (int j = 0; j < 4; j++)
                    wmma::mma_sync(acc[i][j], af[i], bf[j], acc[i][j]);
        }
        __syncthreads();
    }

    #pragma unroll
    for (int i = 0; i < 2; i++) {
        #pragma unroll
        for (int j = 0; j < 4; j++) {
            wmma::store_matrix_sync(&stage[warp][0], acc[i][j], LDS_STAGE,
                                    wmma::mem_row_major);
            __syncwarp();
            const int r = lane >> 1, c = (lane & 1) * 8;
            const float* sp = &stage[warp][r * LDS_STAGE + c];
            __half2 h[4];
            #pragma unroll
            for (int x = 0; x < 4; x++)
                h[x] = __float22half2_rn(make_float2(sp[2 * x], sp[2 * x + 1]));
            __half* cp = C + (size_t)(block_row + wm * 32 + 16 * i + r) * DD
                       + block_col + wn * 64 + 16 * j + c;
            *(uint4*)cp = *(uint4*)h;
            __syncwarp();
        }
    }
}

// ---------------- K2: fused edge scores + exp + segment scatter -------------
// Lane-per-(edge,head): 8 lanes per edge, 4 edges per warp. Each lane owns one
// head = 32 contiguous halves (64B) of q and k -> full dot in registers, no
// reduction shuffles. Coalesced out store; v4 seg atomics (2 per edge).
__device__ __forceinline__ float hdot8(uint4 q, uint4 k) {
    const __half2* qh = (const __half2*)&q;
    const __half2* kh = (const __half2*)&k;
    float s = 0.0f;
    #pragma unroll
    for (int j = 0; j < 4; j++) {
        float2 qf = __half22float2(qh[j]);
        float2 kf = __half22float2(kh[j]);
        s = fmaf(qf.x, kf.x, s);
        s = fmaf(qf.y, kf.y, s);
    }
    return s;
}

__global__ void __launch_bounds__(256)
edge_fused_kernel(float* __restrict__ out) {
    const int gtid = blockIdx.x * blockDim.x + threadIdx.x;
    const int lane = threadIdx.x & 31;
    const int e_glob = gtid >> 3;          // edge index; grid exact (TOTAL_E%4==0)
    const int h = lane & 7;                // head owned by this lane

    const int b = (e_glob >= MM) ? 1 : 0;
    const int m = e_glob - b * MM;
    const int i0 = g_mask32[m];
    const int i1 = g_mask32[MM + m];

    const uint4* q4 = (const uint4*)(g_qh + ((size_t)b * NN + i0) * DD) + h * 4;
    const uint4* k4 = (const uint4*)(g_kh + ((size_t)b * NN + i1) * DD) + h * 4;

    uint4 qv0 = q4[0], qv1 = q4[1], qv2 = q4[2], qv3 = q4[3];
    uint4 kv0 = k4[0], kv1 = k4[1], kv2 = k4[2], kv3 = k4[3];

    float p = hdot8(qv0, kv0) + hdot8(qv1, kv1)
            + hdot8(qv2, kv2) + hdot8(qv3, kv3);

    const float e = __expf(p * 0.0625f);   // / sqrt(256); max-sub dropped
    out[(size_t)e_glob * HH + h] = e;      // == base*8 + lane: coalesced 128B

    // gather 4 consecutive head values into every lane with lane%4==0
    const int gbase = lane & ~3;
    float4 vv;
    vv.x = __shfl_sync(0xffffffffu, e, gbase + 0);
    vv.y = __shfl_sync(0xffffffffu, e, gbase + 1);
    vv.z = __shfl_sync(0xffffffffu, e, gbase + 2);
    vv.w = __shfl_sync(0xffffffffu, e, gbase + 3);

    if ((lane & 3) == 0) {
        float* segp = g_seg + ((size_t)b * NN + i0) * HH + (h & 4);
        asm volatile("red.global.add.v4.f32 [%0], {%1, %2, %3, %4};"
                     :: "l"(segp), "f"(vv.x), "f"(vv.y), "f"(vv.z), "f"(vv.w)
                     : "memory");
    }
}

// ---------------- K3: out = e / (seg[idx] + 1e-16) in place ------------------
__global__ void __launch_bounds__(256)
normalize_kernel(float* __restrict__ e) {
    const int t = blockIdx.x * blockDim.x + threadIdx.x;
    if (t >= TOTAL_E) return;
    const int b = t / MM;
    const int m = t - b * MM;
    const int i0 = g_mask32[m];

    const float4* segp = (const float4*)(g_seg + ((size_t)b * NN + i0) * HH);
    float4 s0 = segp[0], s1 = segp[1];

    const size_t base = (size_t)t * HH;
    float4 e0 = *(float4*)(e + base);
    float4 e1 = *(float4*)(e + base + 4);

    e0.x /= (s0.x + 1e-16f);
    e0.y /= (s0.y + 1e-16f);
    e0.z /= (s0.z + 1e-16f);
    e0.w /= (s0.w + 1e-16f);
    e1.x /= (s1.x + 1e-16f);
    e1.y /= (s1.y + 1e-16f);
    e1.z /= (s1.z + 1e-16f);
    e1.w /= (s1.w + 1e-16f);

    *(float4*)(e + base)     = e0;
    *(float4*)(e + base + 4) = e1;
}

// ---------------- launch ----------------------------------------------------
extern "C" void kernel_launch(void* const* d_in, const int* in_sizes, int n_in,
                              void* d_out, int out_size) {
    const float* x_q  = (const float*)d_in[0];
    const float* x_k  = (const float*)d_in[1];
    const void*  mask = (const void*)d_in[2];
    const float* w_q  = (const float*)d_in[3];
    const float* w_k  = (const float*)d_in[4];
    float* out = (float*)d_out;

    // K_pre: detect mask dtype, normalize to int32, zero seg, fp16 convert
    detect_mask_kernel<<<1, 256>>>((const unsigned*)mask);
    convert_mask_kernel<<<(2 * MM + 255) / 256, 256>>>(mask);
    {
        int total = 2 * MPAD * (DD / 8) + 2 * (DD * DD / 8);
        convert_inputs_kernel<<<(total + 255) / 256, 256>>>(x_q, x_k, w_q, w_k);
    }
    // K1: q = x_q@w_q, k = x_k@w_k on tensor cores
    {
        dim3 grid(MPAD / 128, DD / 128, 2);
        gemm_wmma_kernel<<<grid, 256>>>();
    }
    // K2: fused edge scores + exp + segment scatter (8 threads per edge)
    {
        long long threads = (long long)TOTAL_E * 8;
        int blocks = (int)((threads + 255) / 256);
        edge_fused_kernel<<<blocks, 256>>>(out);
    }
    // K3: normalize
    {
        int blocks = (TOTAL_E + 255) / 256;
        normalize_kernel<<<blocks, 256>>>(out);
    }
}

// round 7
// speedup vs baseline: 1.0620x; 1.0620x over previous
#include <cuda_runtime.h>
#include <cuda_fp16.h>
#include <mma.h>
#include <cstdint>

using namespace nvcuda;

// Problem constants
#define BB 2
#define NN 10000
#define MM 320000
#define DD 256
#define HH 8
#define ROWS (BB * NN)          // 20000 flattened GEMM rows
#define MPAD 20096              // 157 * 128: padded so GEMM needs no guards
#define TOTAL_E (BB * MM)       // 640000 (b, edge) pairs
#define BK 32
#define LDA 40                  // As padded stride (halves): 80B, conflict-free LDSM
#define LDB 136                 // Bs padded stride (halves): 272B, conflict-free LDSM
#define LDS_STAGE 20            // epilogue staging stride (floats)

// ---------------- scratch (device globals; no allocation allowed) ----------
__device__ __half g_xh[2 * (size_t)MPAD * DD];  // fp16 x_q | x_k (padded rows zeroed)
__device__ __half g_wh[2 * DD * DD];            // fp16 w_q | w_k
__device__ __half g_qh[(size_t)MPAD * DD];      // fp16 q
__device__ __half g_kh[(size_t)MPAD * DD];      // fp16 k
__device__ float  g_seg[(size_t)BB * NN * HH];  // 640 KB
__device__ int    g_mask32[2 * MM];             // canonical int32 mask
__device__ int    g_is64;                       // detected mask dtype

// ---------------- K_pre0: detect mask dtype ---------------------------------
// int64 indices in [0,N): every odd 32-bit word is 0. int32: odd words random.
__global__ void detect_mask_kernel(const unsigned* __restrict__ mraw) {
    __shared__ int any_nonzero;
    if (threadIdx.x == 0) any_nonzero = 0;
    __syncthreads();
    unsigned v = mraw[threadIdx.x * 2 + 1];
    if (v != 0u) atomicOr(&any_nonzero, 1);
    __syncthreads();
    if (threadIdx.x == 0) g_is64 = any_nonzero ? 0 : 1;
}

// ---------------- K_pre1: normalize mask to int32 (clamped) + reset seg -----
__global__ void convert_mask_kernel(const void* __restrict__ mraw) {
    int t = blockIdx.x * blockDim.x + threadIdx.x;
    if (t < 2 * MM) {
        long long v;
        if (g_is64) v = ((const long long*)mraw)[t];
        else        v = (long long)((const int*)mraw)[t];
        int vi = (int)v;
        vi = vi < 0 ? 0 : (vi >= NN ? NN - 1 : vi);
        g_mask32[t] = vi;
    }
    if (t < BB * NN * HH) g_seg[t] = 0.0f;
}

// ---------------- K_pre2: fp32 -> fp16 conversion of x and w ----------------
__global__ void convert_inputs_kernel(const float* __restrict__ xq,
                                      const float* __restrict__ xk,
                                      const float* __restrict__ wq,
                                      const float* __restrict__ wk) {
    const int t = blockIdx.x * blockDim.x + threadIdx.x;
    const int XT = 2 * MPAD * (DD / 8);   // threads covering x region
    if (t < XT) {
        const int per_mat = MPAD * (DD / 8);
        const int mat = t / per_mat;
        const int r   = (t % per_mat) / (DD / 8);
        const int c   = (t % (DD / 8)) * 8;
        __half2 h[4];
        if (r < ROWS) {
            const float* src = (mat == 0 ? xq : xk) + (size_t)r * DD + c;
            float4 f0 = *(const float4*)(src);
            float4 f1 = *(const float4*)(src + 4);
            h[0] = __float22half2_rn(make_float2(f0.x, f0.y));
            h[1] = __float22half2_rn(make_float2(f0.z, f0.w));
            h[2] = __float22half2_rn(make_float2(f1.x, f1.y));
            h[3] = __float22half2_rn(make_float2(f1.z, f1.w));
        } else {
            h[0] = h[1] = h[2] = h[3] = __float2half2_rn(0.0f);
        }
        *(uint4*)(g_xh + (size_t)mat * MPAD * DD + (size_t)r * DD + c) = *(uint4*)h;
    } else {
        const int u = t - XT;
        const int WT = 2 * (DD * DD / 8);
        if (u < WT) {
            const int per_mat = DD * DD / 8;
            const int mat = u / per_mat;
            const int e   = (u % per_mat) * 8;
            const float* src = (mat == 0 ? wq : wk) + e;
            float4 f0 = *(const float4*)(src);
            float4 f1 = *(const float4*)(src + 4);
            __half2 h[4];
            h[0] = __float22half2_rn(make_float2(f0.x, f0.y));
            h[1] = __float22half2_rn(make_float2(f0.z, f0.w));
            h[2] = __float22half2_rn(make_float2(f1.x, f1.y));
            h[3] = __float22half2_rn(make_float2(f1.z, f1.w));
            *(uint4*)(g_wh + (size_t)mat * DD * DD + e) = *(uint4*)h;
        }
    }
}

// ---------------- K1: HMMA GEMM  C = A(fp16) * W(fp16), fp32 acc, fp16 out --
// BM=128, BN=128, BK=32. 8 warps in 4x2, each owns 32x64 (2x4 wmma frags).
// Padded smem strides (LDA=40, LDB=136) -> conflict-free LDSM. Register
// prefetch of next k-tile. No bounds checks (M padded to MPAD).
__global__ void __launch_bounds__(256)
gemm_wmma_kernel() {
    const int mat = blockIdx.z;
    const __half* A = g_xh + (size_t)mat * MPAD * DD;
    const __half* B = g_wh + (size_t)mat * DD * DD;
    __half*       C = (mat == 0) ? g_qh : g_kh;

    __shared__ __half As[128 * LDA];            // padded: 10 KB
    __shared__ __half Bs[BK * LDB];             // padded: 8.5 KB
    __shared__ float  stage[8][16 * LDS_STAGE]; // per-warp staging, 10 KB

    const int tid  = threadIdx.x;
    const int warp = tid >> 5;
    const int lane = tid & 31;
    const int wm = warp >> 1;          // 0..3
    const int wn = warp & 1;           // 0..1
    const int block_row = blockIdx.x * 128;
    const int block_col = blockIdx.y * 128;

    const int a_r = tid >> 1;
    const int a_c = (tid & 1) * 16;
    const __half* a_src = A + (size_t)(block_row + a_r) * DD + a_c;
    const int b_r0 = tid >> 4,          b_c0 = (tid & 15) * 8;
    const int b_r1 = (tid + 256) >> 4,  b_c1 = ((tid + 256) & 15) * 8;
    const __half* b_src0 = B + (size_t)b_r0 * DD + block_col + b_c0;
    const __half* b_src1 = B + (size_t)b_r1 * DD + block_col + b_c1;

    wmma::fragment<wmma::accumulator, 16, 16, 16, float> acc[2][4];
    #pragma unroll
    for (int i = 0; i < 2; i++)
        #pragma unroll
        for (int j = 0; j < 4; j++) wmma::fill_fragment(acc[i][j], 0.0f);

    uint4 av0 = *(const uint4*)(a_src);
    uint4 av1 = *(const uint4*)(a_src + 8);
    uint4 bv0 = *(const uint4*)(b_src0);
    uint4 bv1 = *(const uint4*)(b_src1);

    for (int k0 = 0; k0 < DD; k0 += BK) {
        *(uint4*)(As + a_r * LDA + a_c)     = av0;
        *(uint4*)(As + a_r * LDA + a_c + 8) = av1;
        *(uint4*)(Bs + b_r0 * LDB + b_c0)   = bv0;
        *(uint4*)(Bs + b_r1 * LDB + b_c1)   = bv1;
        __syncthreads();

        if (k0 + BK < DD) {            // issue next tile's loads early
            av0 = *(const uint4*)(a_src + k0 + BK);
            av1 = *(const uint4*)(a_src + k0 + BK + 8);
            bv0 = *(const uint4*)(b_src0 + (size_t)(k0 + BK) * DD);
            bv1 = *(const uint4*)(b_src1 + (size_t)(k0 + BK) * DD);
        }

        #pragma unroll
        for (int kk = 0; kk < BK; kk += 16) {
            wmma::fragment<wmma::matrix_a, 16, 16, 16, __half, wmma::row_major> af[2];
            wmma::fragment<wmma::matrix_b, 16, 16, 16, __half, wmma::row_major> bf[4];
            #pragma unroll
            for (int i = 0; i < 2; i++)
                wmma::load_matrix_sync(af[i], As + (wm * 32 + 16 * i) * LDA + kk, LDA);
            #pragma unroll
            for (int j = 0; j < 4; j++)
                wmma::load_matrix_sync(bf[j], Bs + kk * LDB + wn * 64 + 16 * j, LDB);
            #pragma unroll
            for (int i = 0; i < 2; i++)
                #pragma unroll
                for (int j = 0; j < 4; j++)
                    wmma::mma_sync(acc[i][j], af[i], bf[j], acc[i][j]);
        }
        __syncthreads();
    }

    #pragma unroll
    for (int i = 0; i < 2; i++) {
        #pragma unroll
        for (int j = 0; j < 4; j++) {
            wmma::store_matrix_sync(&stage[warp][0], acc[i][j], LDS_STAGE,
                                    wmma::mem_row_major);
            __syncwarp();
            const int r = lane >> 1, c = (lane & 1) * 8;
            const float* sp = &stage[warp][r * LDS_STAGE + c];
            __half2 h[4];
            #pragma unroll
            for (int x = 0; x < 4; x++)
                h[x] = __float22half2_rn(make_float2(sp[2 * x], sp[2 * x + 1]));
            __half* cp = C + (size_t)(block_row + wm * 32 + 16 * i + r) * DD
                       + block_col + wn * 64 + 16 * j + c;
            *(uint4*)cp = *(uint4*)h;
            __syncwarp();
        }
    }
}

// ---------------- K2: fused edge scores + exp + segment scatter -------------
// One warp per (b, edge) [proven coalesced layout]. Per-lane dot now runs in
// native half2 (4 HFMA2) with a single fp32 fold at the end, cutting the
// fma/cvt instruction stream ~40%. Cross-lane reduction stays fp32.
__device__ __forceinline__ float hdot8_h2(uint4 q, uint4 k) {
    const __half2* qh = (const __half2*)&q;
    const __half2* kh = (const __half2*)&k;
    __half2 acc = __hmul2(qh[0], kh[0]);
    acc = __hfma2(qh[1], kh[1], acc);
    acc = __hfma2(qh[2], kh[2], acc);
    acc = __hfma2(qh[3], kh[3], acc);
    return __low2float(acc) + __high2float(acc);
}

__global__ void __launch_bounds__(256)
edge_fused_kernel(float* __restrict__ out) {
    const int warp = (blockIdx.x * blockDim.x + threadIdx.x) >> 5;
    const int lane = threadIdx.x & 31;
    if (warp >= TOTAL_E) return;

    const int b = warp / MM;
    const int m = warp - b * MM;
    const int i0 = g_mask32[m];
    const int i1 = g_mask32[MM + m];

    const uint4* q4 = (const uint4*)(g_qh + ((size_t)b * NN + i0) * DD);
    const uint4* k4 = (const uint4*)(g_kh + ((size_t)b * NN + i1) * DD);

    float p = hdot8_h2(q4[lane], k4[lane]);

    // reduce within 4-lane head groups (head = 32 contiguous halves)
    p += __shfl_down_sync(0xffffffffu, p, 2, 4);
    p += __shfl_down_sync(0xffffffffu, p, 1, 4);

    float e = 0.0f;
    if ((lane & 3) == 0) {
        e = __expf(p * 0.0625f);                       // / sqrt(256); no max-sub
        out[(size_t)warp * HH + (lane >> 2)] = e;      // head = lane/4
    }

    // gather 4 head values into lanes 0 (heads 0-3) and 16 (heads 4-7)
    float4 vv;
    vv.x = __shfl_sync(0xffffffffu, e, (lane & 16) + 0);
    vv.y = __shfl_sync(0xffffffffu, e, (lane & 16) + 4);
    vv.z = __shfl_sync(0xffffffffu, e, (lane & 16) + 8);
    vv.w = __shfl_sync(0xffffffffu, e, (lane & 16) + 12);

    if ((lane & 15) == 0) {
        float* segp = g_seg + ((size_t)b * NN + i0) * HH + (lane >> 2);
        asm volatile("red.global.add.v4.f32 [%0], {%1, %2, %3, %4};"
                     :: "l"(segp), "f"(vv.x), "f"(vv.y), "f"(vv.z), "f"(vv.w)
                     : "memory");
    }
}

// ---------------- K3: out = e / (seg[idx] + 1e-16) in place ------------------
__global__ void __launch_bounds__(256)
normalize_kernel(float* __restrict__ e) {
    const int t = blockIdx.x * blockDim.x + threadIdx.x;
    if (t >= TOTAL_E) return;
    const int b = t / MM;
    const int m = t - b * MM;
    const int i0 = g_mask32[m];

    const float4* segp = (const float4*)(g_seg + ((size_t)b * NN + i0) * HH);
    float4 s0 = segp[0], s1 = segp[1];

    const size_t base = (size_t)t * HH;
    float4 e0 = *(float4*)(e + base);
    float4 e1 = *(float4*)(e + base + 4);

    e0.x /= (s0.x + 1e-16f);
    e0.y /= (s0.y + 1e-16f);
    e0.z /= (s0.z + 1e-16f);
    e0.w /= (s0.w + 1e-16f);
    e1.x /= (s1.x + 1e-16f);
    e1.y /= (s1.y + 1e-16f);
    e1.z /= (s1.z + 1e-16f);
    e1.w /= (s1.w + 1e-16f);

    *(float4*)(e + base)     = e0;
    *(float4*)(e + base + 4) = e1;
}

// ---------------- launch ----------------------------------------------------
extern "C" void kernel_launch(void* const* d_in, const int* in_sizes, int n_in,
                              void* d_out, int out_size) {
    const float* x_q  = (const float*)d_in[0];
    const float* x_k  = (const float*)d_in[1];
    const void*  mask = (const void*)d_in[2];
    const float* w_q  = (const float*)d_in[3];
    const float* w_k  = (const float*)d_in[4];
    float* out = (float*)d_out;

    // K_pre: detect mask dtype, normalize to int32, zero seg, fp16 convert
    detect_mask_kernel<<<1, 256>>>((const unsigned*)mask);
    convert_mask_kernel<<<(2 * MM + 255) / 256, 256>>>(mask);
    {
        int total = 2 * MPAD * (DD / 8) + 2 * (DD * DD / 8);
        convert_inputs_kernel<<<(total + 255) / 256, 256>>>(x_q, x_k, w_q, w_k);
    }
    // K1: q = x_q@w_q, k = x_k@w_k on tensor cores
    {
        dim3 grid(MPAD / 128, DD / 128, 2);
        gemm_wmma_kernel<<<grid, 256>>>();
    }
    // K2: fused edge scores + exp + segment scatter (warp per edge)
    {
        int warps_per_block = 256 / 32;
        int blocks = (TOTAL_E + warps_per_block - 1) / warps_per_block;
        edge_fused_kernel<<<blocks, 256>>>(out);
    }
    // K3: normalize
    {
        int blocks = (TOTAL_E + 255) / 256;
        normalize_kernel<<<blocks, 256>>>(out);
    }
}